// round 7
// baseline (speedup 1.0000x reference)
#include <cuda_runtime.h>
#include <cuda_bf16.h>
#include <cuda_fp16.h>
#include <math.h>
#include <stdint.h>

// Problem constants
#define BB 16
#define TT 256
#define EE 256
#define HH 512
#define G4H 2048
#define VV 32000
#define MROWS 4096           // B*T, row r = t*16 + b
#define NC1 64               // layer-1 CTA group
#define NC2 64               // layer-2 CTA group

// ------------------------- scratch (no mallocs allowed) -------------------------
__device__ float g_xw[(size_t)MROWS * G4H];     // xw1 = emb@W1+b1
__device__ float g_h1r[4][BB * HH];             // h1 ring (depth 4)
__device__ float g_h2r[2][BB * HH];             // h2 ping-pong
__device__ int g_s1done, g_s2done;              // step progress flags
__device__ unsigned g_b1c, g_b1g;               // group-1 barrier
__device__ unsigned g_b2c, g_b2g;               // group-2 barrier

// fp16 operands for the tensor-core dense layer
__device__ __half g_a_h[(size_t)MROWS * HH];    // 4 MB  (written by LSTM layer 2)
__device__ __half g_b_h[(size_t)VV * HH];       // 32.8 MB, [v][h] transposed Wd

// ------------------------- small PTX helpers ------------------------------------
__device__ __forceinline__ uint32_t smem_u32(const void* p) {
    uint32_t a;
    asm("{ .reg .u64 t; cvta.to.shared.u64 t, %1; cvt.u32.u64 %0, t; }" : "=r"(a) : "l"(p));
    return a;
}
__device__ __forceinline__ void cp_async16(uint32_t saddr, const void* gptr) {
    asm volatile("cp.async.cg.shared.global [%0], [%1], 16;"
                 :: "r"(saddr), "l"(__cvta_generic_to_global(gptr)) : "memory");
}
__device__ __forceinline__ void cp_commit() {
    asm volatile("cp.async.commit_group;" ::: "memory");
}
template<int N>
__device__ __forceinline__ void cp_wait() {
    asm volatile("cp.async.wait_group %0;" :: "n"(N) : "memory");
}
__device__ __forceinline__ void ldm_x4(uint32_t* r, uint32_t a) {
    asm volatile("ldmatrix.sync.aligned.m8n8.x4.shared.b16 {%0,%1,%2,%3}, [%4];"
                 : "=r"(r[0]), "=r"(r[1]), "=r"(r[2]), "=r"(r[3]) : "r"(a));
}
__device__ __forceinline__ void mma_f16(float* d, const uint32_t* a, uint32_t b0, uint32_t b1) {
    asm volatile(
        "mma.sync.aligned.m16n8k16.row.col.f32.f16.f16.f32 "
        "{%0,%1,%2,%3}, {%4,%5,%6,%7}, {%8,%9}, {%0,%1,%2,%3};"
        : "+f"(d[0]), "+f"(d[1]), "+f"(d[2]), "+f"(d[3])
        : "r"(a[0]), "r"(a[1]), "r"(a[2]), "r"(a[3]), "r"(b0), "r"(b1));
}
// packed fp32x2 (Blackwell): 2 MACs per instruction
typedef unsigned long long ull;
__device__ __forceinline__ ull pk2(float lo, float hi) {
    ull r;
    asm("mov.b64 %0, {%1, %2};" : "=l"(r) : "f"(lo), "f"(hi));
    return r;
}
__device__ __forceinline__ ull fma2(ull a, ull b, ull c) {
    ull d;
    asm("fma.rn.f32x2 %0, %1, %2, %3;" : "=l"(d) : "l"(a), "l"(b), "l"(c));
    return d;
}
__device__ __forceinline__ float sum2(ull a) {
    float lo, hi;
    asm("mov.b64 {%0, %1}, %2;" : "=f"(lo), "=f"(hi) : "l"(a));
    return lo + hi;
}
__device__ __forceinline__ void lds_v2u64(ull& a, ull& b, uint32_t addr) {
    asm volatile("ld.shared.v2.u64 {%0, %1}, [%2];" : "=l"(a), "=l"(b) : "r"(addr));
}

// ------------------------- group barrier ----------------------------------------
__device__ __forceinline__ void group_barrier(unsigned* cnt, unsigned* gen, int n) {
    __syncthreads();
    if (threadIdx.x == 0) {
        __threadfence();
        unsigned g = *(volatile unsigned*)gen;
        if (atomicAdd(cnt, 1u) == (unsigned)(n - 1)) {
            *cnt = 0;
            __threadfence();
            *(volatile unsigned*)gen = g + 1u;
        } else {
            while (*(volatile unsigned*)gen == g) { }
            __threadfence();
        }
    }
    __syncthreads();
}

// ------------------------- prep: sgemm0 (xw1) + transB fused --------------------
// blocks [0,512): 128x128 fp32 GEMM tile of xw1 = gather(emb)@W1 + b1
// blocks [512, 16512): 32x32 transpose tiles of Wd -> g_b_h fp16
__global__ __launch_bounds__(256, 2)
void prep_kernel(const float* __restrict__ emb,
                 const float* __restrict__ W1,
                 const float* __restrict__ b1,
                 const int* __restrict__ tokens,
                 const float* __restrict__ Wd)
{
    const int bid = blockIdx.x;
    const int tid = threadIdx.x;

    if (bid >= 512) {
        // ---- transB role ----
        __shared__ __half sh[32][33];
        int tb = bid - 512;
        int v0 = (tb % 1000) * 32;
        int h0 = (tb / 1000) * 32;
        int tx = tid & 31, ty = tid >> 5;
#pragma unroll
        for (int j = 0; j < 4; j++) {
            int hr = ty + j * 8;
            sh[hr][tx] = __float2half(Wd[(size_t)(h0 + hr) * VV + v0 + tx]);
        }
        __syncthreads();
#pragma unroll
        for (int j = 0; j < 4; j++) {
            int vr = ty + j * 8;
            g_b_h[(size_t)(v0 + vr) * HH + h0 + tx] = sh[tx][vr];
        }
        return;
    }

    // ---- sgemm0 role ----
    if (bid == 0 && tid == 0) { g_s1done = -1; g_s2done = -1; }

    const int K = EE, N = G4H;
    __shared__ float As[16][128];
    __shared__ float Bs[16][128];

    const int m0 = (bid >> 4) * 128;
    const int n0 = (bid & 15) * 128;
    const int rg = (tid >> 4) * 4;
    const int cg = (tid & 15) * 4;

    float acc[8][8];
#pragma unroll
    for (int i = 0; i < 8; i++)
#pragma unroll
        for (int j = 0; j < 8; j++) acc[i][j] = 0.f;

    for (int kt = 0; kt < K; kt += 16) {
        __syncthreads();
#pragma unroll
        for (int it = 0; it < 2; it++) {
            int item = tid + it * 256;
            int m = item >> 2;
            int kq = item & 3;
            int gr = m0 + m;
            int tok = tokens[((gr & 15) << 8) + (gr >> 4)];
            float4 v = *(const float4*)(emb + (size_t)tok * K + kt + kq * 4);
            As[kq * 4 + 0][m] = v.x;
            As[kq * 4 + 1][m] = v.y;
            As[kq * 4 + 2][m] = v.z;
            As[kq * 4 + 3][m] = v.w;
        }
#pragma unroll
        for (int it = 0; it < 2; it++) {
            int item = tid + it * 256;
            int k = item >> 5;
            int n4 = item & 31;
            float4 v = *(const float4*)(W1 + (size_t)(kt + k) * N + n0 + n4 * 4);
            *(float4*)&Bs[k][n4 * 4] = v;
        }
        __syncthreads();
#pragma unroll
        for (int kk = 0; kk < 16; kk++) {
            float4 a0 = *(const float4*)&As[kk][rg];
            float4 a1 = *(const float4*)&As[kk][64 + rg];
            float4 b0 = *(const float4*)&Bs[kk][cg];
            float4 b1 = *(const float4*)&Bs[kk][64 + cg];
            float a[8] = {a0.x, a0.y, a0.z, a0.w, a1.x, a1.y, a1.z, a1.w};
            float b[8] = {b0.x, b0.y, b0.z, b0.w, b1.x, b1.y, b1.z, b1.w};
#pragma unroll
            for (int i = 0; i < 8; i++)
#pragma unroll
                for (int j = 0; j < 8; j++)
                    acc[i][j] += a[i] * b[j];
        }
    }

    float bj[8];
#pragma unroll
    for (int j = 0; j < 4; j++) {
        bj[j]     = b1[n0 + cg + j];
        bj[4 + j] = b1[n0 + 64 + cg + j];
    }
#pragma unroll
    for (int i = 0; i < 8; i++) {
        int r = m0 + ((i < 4) ? (rg + i) : (64 + rg + i - 4));
        float4 o0, o1;
        o0.x = acc[i][0] + bj[0]; o0.y = acc[i][1] + bj[1];
        o0.z = acc[i][2] + bj[2]; o0.w = acc[i][3] + bj[3];
        o1.x = acc[i][4] + bj[4]; o1.y = acc[i][5] + bj[5];
        o1.z = acc[i][6] + bj[6]; o1.w = acc[i][7] + bj[7];
        *(float4*)&g_xw[(size_t)r * N + n0 + cg]      = o0;
        *(float4*)&g_xw[(size_t)r * N + n0 + 64 + cg] = o1;
    }
}

// ------------------------- split-group dual LSTM --------------------------------
// Grid = 128 CTAs x 512 threads, all resident.
//   CTAs [0,64):   layer-1 recurrence; CTA owns 8 hidden units (32 gate cols).
//   CTAs [64,128): layer-2 recurrence; consumes h1[t] via g_s1done flag.
// Thread (ks = tid/32 in 0..15, lc = tid%32): 32 k-values per matrix in f32x2 regs.
// Smem floats: hs1 8192 | hs2 8192 | p 8192 | zsh 512 | cs 128  = 25216 (100.8 KB)
#define LSM_FLOATS 25216
__global__ __launch_bounds__(512, 1)
void lstm_split_kernel(const float* __restrict__ U1,
                       const float* __restrict__ W2,
                       const float* __restrict__ U2,
                       const float* __restrict__ b2)
{
    extern __shared__ float ls[];
    float* hs1 = ls;
    float* hs2 = ls + 8192;
    float* p   = ls + 16384;
    float* zsh = ls + 24576;
    float* cs  = ls + 25088;

    const int tid = threadIdx.x;
    const int bid = blockIdx.x;
    const bool is1 = bid < NC1;
    const int ctg = is1 ? bid : bid - NC1;
    const int hu0 = ctg * 8;
    const int ks = tid >> 5;            // 0..15  (k-slice of 32)
    const int lc = tid & 31;            // 0..31  (gate col: gate*8 + unit)
    const int gc = ((lc >> 3) << 9) + hu0 + (lc & 7);
    const uint32_t hs1_a = smem_u32(hs1);
    const uint32_t hs2_a = smem_u32(hs2);
    const int k0 = ks * 32;

    if (tid < 128) cs[tid] = 0.f;

    if (is1) {
        // -------- layer 1: z1 = xw1[s] + h1[s-1]@U1 --------
        ull wu[16];
#pragma unroll
        for (int j = 0; j < 16; j++) {
            int kk = k0 + 2 * j;
            wu[j] = pk2(U1[(size_t)kk * G4H + gc], U1[(size_t)(kk + 1) * G4H + gc]);
        }
        __syncthreads();

        for (int s = 0; s < TT; s++) {
            float xwv = __ldg(&g_xw[((size_t)s * BB + ks) * G4H + gc]);

            if (s >= 1) {
                const float* hp = g_h1r[(s - 1) & 3];
#pragma unroll
                for (int i = 0; i < 4; i++) {
                    int u = tid + i * 512;
                    cp_async16(hs1_a + (uint32_t)u * 16u, hp + u * 4);
                }
                cp_commit();
                cp_wait<0>();
                __syncthreads();
#pragma unroll 2
                for (int b = 0; b < 16; b++) {
                    uint32_t a = hs1_a + (uint32_t)(b * 2048 + k0 * 4);
                    ull acc = 0;
#pragma unroll
                    for (int j = 0; j < 4; j++) {
                        ull q0, q1, q2, q3;
                        lds_v2u64(q0, q1, a + (uint32_t)(j * 32));
                        lds_v2u64(q2, q3, a + (uint32_t)(j * 32 + 16));
                        acc = fma2(q0, wu[4 * j + 0], acc);
                        acc = fma2(q1, wu[4 * j + 1], acc);
                        acc = fma2(q2, wu[4 * j + 2], acc);
                        acc = fma2(q3, wu[4 * j + 3], acc);
                    }
                    p[b * 512 + ks * 32 + lc] = sum2(acc);
                }
                __syncthreads();
            }

            float z = xwv;
            if (s >= 1) {
#pragma unroll
                for (int k2 = 0; k2 < 16; k2++)
                    z += p[ks * 512 + k2 * 32 + lc];
            }
            zsh[ks * 32 + lc] = z;

            // back-pressure: don't overwrite ring slot layer-2 hasn't consumed
            if (tid == 0) {
                while (*(volatile int*)&g_s2done < s - 4) { }
            }
            __syncthreads();

            if (tid < 128) {
                int b = tid >> 3, u = tid & 7;
                float zi = zsh[b * 32 + u];
                float zf = zsh[b * 32 + 8 + u];
                float zg = zsh[b * 32 + 16 + u];
                float zo = zsh[b * 32 + 24 + u];
                float ig = 1.f / (1.f + expf(-zi));
                float fg = 1.f / (1.f + expf(-zf));
                float gg = tanhf(zg);
                float og = 1.f / (1.f + expf(-zo));
                float c = fg * cs[tid] + ig * gg;
                cs[tid] = c;
                g_h1r[s & 3][b * HH + hu0 + u] = og * tanhf(c);
            }
            group_barrier(&g_b1c, &g_b1g, NC1);
            if (ctg == 0 && tid == 0) {
                __threadfence();
                *(volatile int*)&g_s1done = s;
            }
        }
    } else {
        // -------- layer 2: z2 = b2 + h1[t]@W2 + h2[t-1]@U2 --------
        ull w2p[16], u2p[16];
#pragma unroll
        for (int j = 0; j < 16; j++) {
            int kk = k0 + 2 * j;
            w2p[j] = pk2(W2[(size_t)kk * G4H + gc], W2[(size_t)(kk + 1) * G4H + gc]);
            u2p[j] = pk2(U2[(size_t)kk * G4H + gc], U2[(size_t)(kk + 1) * G4H + gc]);
        }
        const float b2v = __ldg(b2 + gc);
        __syncthreads();

        for (int t = 0; t < TT; t++) {
            // stage h2[t-1] first (own group's data, ready after previous barrier)
            if (t >= 1) {
                const float* hq = g_h2r[(t - 1) & 1];
#pragma unroll
                for (int i = 0; i < 4; i++) {
                    int u = tid + i * 512;
                    cp_async16(hs2_a + (uint32_t)u * 16u, hq + u * 4);
                }
                cp_commit();
            }
            // wait for layer-1 to publish h1[t]
            if (tid == 0) {
                while (*(volatile int*)&g_s1done < t) { }
                __threadfence();
            }
            __syncthreads();
            {
                const float* hp = g_h1r[t & 3];
#pragma unroll
                for (int i = 0; i < 4; i++) {
                    int u = tid + i * 512;
                    cp_async16(hs1_a + (uint32_t)u * 16u, hp + u * 4);
                }
                cp_commit();
            }
            cp_wait<0>();
            __syncthreads();

#pragma unroll 2
            for (int b = 0; b < 16; b++) {
                uint32_t a1 = hs1_a + (uint32_t)(b * 2048 + k0 * 4);
                ull accw = 0;
#pragma unroll
                for (int j = 0; j < 4; j++) {
                    ull q0, q1, q2, q3;
                    lds_v2u64(q0, q1, a1 + (uint32_t)(j * 32));
                    lds_v2u64(q2, q3, a1 + (uint32_t)(j * 32 + 16));
                    accw = fma2(q0, w2p[4 * j + 0], accw);
                    accw = fma2(q1, w2p[4 * j + 1], accw);
                    accw = fma2(q2, w2p[4 * j + 2], accw);
                    accw = fma2(q3, w2p[4 * j + 3], accw);
                }
                float pv = sum2(accw);
                if (t >= 1) {
                    uint32_t a2 = hs2_a + (uint32_t)(b * 2048 + k0 * 4);
                    ull accu = 0;
#pragma unroll
                    for (int j = 0; j < 4; j++) {
                        ull r0, r1, r2, r3;
                        lds_v2u64(r0, r1, a2 + (uint32_t)(j * 32));
                        lds_v2u64(r2, r3, a2 + (uint32_t)(j * 32 + 16));
                        accu = fma2(r0, u2p[4 * j + 0], accu);
                        accu = fma2(r1, u2p[4 * j + 1], accu);
                        accu = fma2(r2, u2p[4 * j + 2], accu);
                        accu = fma2(r3, u2p[4 * j + 3], accu);
                    }
                    pv += sum2(accu);
                }
                p[b * 512 + ks * 32 + lc] = pv;
            }
            __syncthreads();

            float z = b2v;
#pragma unroll
            for (int k2 = 0; k2 < 16; k2++)
                z += p[ks * 512 + k2 * 32 + lc];
            zsh[ks * 32 + lc] = z;
            __syncthreads();

            if (tid < 128) {
                int b = tid >> 3, u = tid & 7;
                float zi = zsh[b * 32 + u];
                float zf = zsh[b * 32 + 8 + u];
                float zg = zsh[b * 32 + 16 + u];
                float zo = zsh[b * 32 + 24 + u];
                float ig = 1.f / (1.f + expf(-zi));
                float fg = 1.f / (1.f + expf(-zf));
                float gg = tanhf(zg);
                float og = 1.f / (1.f + expf(-zo));
                float c = fg * cs[tid] + ig * gg;
                cs[tid] = c;
                float h = og * tanhf(c);
                g_h2r[t & 1][b * HH + hu0 + u] = h;
                g_a_h[((size_t)t * BB + b) * HH + hu0 + u] = __float2half(h);
            }
            group_barrier(&g_b2c, &g_b2g, NC2);
            if (ctg == 0 && tid == 0) {
                __threadfence();
                *(volatile int*)&g_s2done = t;
            }
        }
    }
}

// ------------------------- HMMA dense GEMM (fp16, 3-stage pipeline) -------------
#define DARR 10240u          // bytes per sub-array (128*80)
#define DSTG 20480u          // bytes per stage (A|B)

__device__ __forceinline__ void dense_load_chunk(uint32_t sb, int m0, int n0, int c, int tid)
{
    const uint32_t stg = sb + (uint32_t)(c % 3) * DSTG;
    const int kc0 = c * 32;
#pragma unroll
    for (int it = 0; it < 4; it++) {
        int u = tid + it * 256;          // 0..1023 16B units
        int arr = u >> 9;                // 0 A, 1 B
        int u2 = u & 511;
        int r = u2 >> 2, q = u2 & 3;
        const __half* g = arr ? g_b_h : g_a_h;
        int grow = arr ? n0 : m0;
        cp_async16(stg + (uint32_t)arr * DARR + (uint32_t)(r * 80 + q * 16),
                   g + (size_t)(grow + r) * HH + kc0 + q * 8);
    }
    cp_commit();
}

__global__ __launch_bounds__(256, 2)
void dense_kernel(const float* __restrict__ bd, float* __restrict__ out)
{
    extern __shared__ char smem[];
    const uint32_t sb = smem_u32(smem);
    const int tid = threadIdx.x;
    const int wid = tid >> 5;
    const int lane = tid & 31;
    const int n0 = blockIdx.x * 128;
    const int m0 = blockIdx.y * 128;
    const int wm = wid & 1;
    const int wn = wid >> 1;
    const int lrow = lane & 15;
    const int lsel = (lane >> 4) << 4;

    float acc[4][4][4];
#pragma unroll
    for (int mt = 0; mt < 4; mt++)
#pragma unroll
        for (int nt = 0; nt < 4; nt++)
#pragma unroll
            for (int e = 0; e < 4; e++) acc[mt][nt][e] = 0.f;

    dense_load_chunk(sb, m0, n0, 0, tid);
    dense_load_chunk(sb, m0, n0, 1, tid);

    for (int c = 0; c < 16; c++) {
        if (c < 15) cp_wait<1>(); else cp_wait<0>();
        __syncthreads();
        if (c + 2 < 16) dense_load_chunk(sb, m0, n0, c + 2, tid);

        const uint32_t stg = sb + (uint32_t)(c % 3) * DSTG;
        const uint32_t a_b = stg + (uint32_t)((wm * 64 + lrow) * 80) + lsel;
        const uint32_t b_b = stg + DARR + (uint32_t)((wn * 32 + lrow) * 80) + lsel;
#pragma unroll
        for (int s = 0; s < 2; s++) {
            uint32_t bf[2][4];
#pragma unroll
            for (int i = 0; i < 2; i++)
                ldm_x4(bf[i], b_b + (uint32_t)(i * 16 * 80 + s * 32));
#pragma unroll
            for (int mt = 0; mt < 4; mt++) {
                uint32_t a[4];
                ldm_x4(a, a_b + (uint32_t)(mt * 16 * 80 + s * 32));
#pragma unroll
                for (int nt = 0; nt < 4; nt++) {
                    uint32_t b0 = bf[nt >> 1][nt & 1];
                    uint32_t b1 = bf[nt >> 1][(nt & 1) + 2];
                    mma_f16(acc[mt][nt], a, b0, b1);
                }
            }
        }
    }

    // epilogue: direct stores with [t*16+b] -> [b*256+t] row remap
    const int g = lane >> 2;
    const int tig = lane & 3;
#pragma unroll
    for (int nt = 0; nt < 4; nt++) {
        int col = n0 + wn * 32 + nt * 8 + tig * 2;
        float b0 = __ldg(bd + col);
        float b1 = __ldg(bd + col + 1);
#pragma unroll
        for (int mt = 0; mt < 4; mt++) {
            int r0 = m0 + wm * 64 + mt * 16 + g;
            int r1 = r0 + 8;
            size_t o0 = (size_t)((r0 & 15) * 256 + (r0 >> 4));
            size_t o1 = (size_t)((r1 & 15) * 256 + (r1 >> 4));
            float2 v0 = make_float2(acc[mt][nt][0] + b0, acc[mt][nt][1] + b1);
            float2 v1 = make_float2(acc[mt][nt][2] + b0, acc[mt][nt][3] + b1);
            *(float2*)(out + o0 * VV + col) = v0;
            *(float2*)(out + o1 * VV + col) = v1;
        }
    }
}

// ------------------------- launch -----------------------------------------------
extern "C" void kernel_launch(void* const* d_in, const int* in_sizes, int n_in,
                              void* d_out, int out_size)
{
    const int*   tokens = (const int*)  d_in[0];
    const float* emb    = (const float*)d_in[1];
    const float* W1     = (const float*)d_in[2];
    const float* U1     = (const float*)d_in[3];
    const float* b1     = (const float*)d_in[4];
    const float* W2     = (const float*)d_in[5];
    const float* U2     = (const float*)d_in[6];
    const float* b2     = (const float*)d_in[7];
    const float* Wd     = (const float*)d_in[8];
    const float* bd     = (const float*)d_in[9];
    float* out = (float*)d_out;

    cudaFuncSetAttribute(dense_kernel, cudaFuncAttributeMaxDynamicSharedMemorySize,
                         (int)(3 * DSTG));
    cudaFuncSetAttribute(lstm_split_kernel, cudaFuncAttributeMaxDynamicSharedMemorySize,
                         (int)(LSM_FLOATS * sizeof(float)));

    // 1) fused prep: xw1 GEMM (+flag reset) and Wd transpose/convert
    prep_kernel<<<512 + 16000, 256>>>(emb, W1, b1, tokens, Wd);
    // 2) split-group dual-layer LSTM; layer 2 writes fp16 g_a_h directly
    lstm_split_kernel<<<NC1 + NC2, 512, LSM_FLOATS * sizeof(float)>>>(U1, W2, U2, b2);
    // 3) logits = h2 @ Wd + bd on HMMA tensor cores (fp16 single pass)
    dense_kernel<<<dim3(VV / 128, MROWS / 128), 256, 3 * DSTG>>>(bd, out);
}

// round 8
// speedup vs baseline: 1.3161x; 1.3161x over previous
#include <cuda_runtime.h>
#include <cuda_bf16.h>
#include <cuda_fp16.h>
#include <math.h>
#include <stdint.h>

// Problem constants
#define BB 16
#define TT 256
#define EE 256
#define HH 512
#define G4H 2048
#define VV 32000
#define MROWS 4096           // B*T, row r = t*16 + b
#define NCTA 128

// ------------------------- scratch (no mallocs allowed) -------------------------
__device__ float g_xw[(size_t)MROWS * G4H];       // xw1 = emb@W1+b1
__device__ __half g_h1rh[2][BB * HH];             // h1 ping-pong (fp16)
__device__ __half g_h2rh[2][BB * HH];             // h2 ping-pong (fp16)
__device__ __half g_ut[3 * (size_t)G4H * HH];     // U1^T|W2^T|U2^T fp16 [gc][k]
__device__ unsigned g_bar_count;
__device__ unsigned g_bar_gen;

// fp16 operands for the tensor-core dense layer
__device__ __half g_a_h[(size_t)MROWS * HH];      // written by LSTM layer-2 gates
__device__ __half g_b_h[(size_t)VV * HH];         // [v][h] transposed Wd

// ------------------------- small PTX helpers ------------------------------------
__device__ __forceinline__ uint32_t smem_u32(const void* p) {
    uint32_t a;
    asm("{ .reg .u64 t; cvta.to.shared.u64 t, %1; cvt.u32.u64 %0, t; }" : "=r"(a) : "l"(p));
    return a;
}
__device__ __forceinline__ void cp_async16(uint32_t saddr, const void* gptr) {
    asm volatile("cp.async.cg.shared.global [%0], [%1], 16;"
                 :: "r"(saddr), "l"(__cvta_generic_to_global(gptr)) : "memory");
}
__device__ __forceinline__ void cp_commit() {
    asm volatile("cp.async.commit_group;" ::: "memory");
}
template<int N>
__device__ __forceinline__ void cp_wait() {
    asm volatile("cp.async.wait_group %0;" :: "n"(N) : "memory");
}
__device__ __forceinline__ void ldm_x4(uint32_t* r, uint32_t a) {
    asm volatile("ldmatrix.sync.aligned.m8n8.x4.shared.b16 {%0,%1,%2,%3}, [%4];"
                 : "=r"(r[0]), "=r"(r[1]), "=r"(r[2]), "=r"(r[3]) : "r"(a));
}
__device__ __forceinline__ void mma_f16(float* d, const uint32_t* a, uint32_t b0, uint32_t b1) {
    asm volatile(
        "mma.sync.aligned.m16n8k16.row.col.f32.f16.f16.f32 "
        "{%0,%1,%2,%3}, {%4,%5,%6,%7}, {%8,%9}, {%0,%1,%2,%3};"
        : "+f"(d[0]), "+f"(d[1]), "+f"(d[2]), "+f"(d[3])
        : "r"(a[0]), "r"(a[1]), "r"(a[2]), "r"(a[3]), "r"(b0), "r"(b1));
}

// ------------------------- global barrier (all CTAs resident) -------------------
__device__ __forceinline__ void grid_barrier(int ncta) {
    __syncthreads();
    if (threadIdx.x == 0) {
        __threadfence();
        unsigned gen = *(volatile unsigned*)&g_bar_gen;
        if (atomicAdd(&g_bar_count, 1u) == (unsigned)(ncta - 1)) {
            g_bar_count = 0;
            __threadfence();
            *(volatile unsigned*)&g_bar_gen = gen + 1u;
        } else {
            while (*(volatile unsigned*)&g_bar_gen == gen) { }
            __threadfence();
        }
    }
    __syncthreads();
}

// ------------------------- prep: sgemm0 + transB(Wd) + transU x3 ----------------
// blocks [0,512): xw1 GEMM tiles; [512,16512): Wd transpose; [16512,19584): U^T fp16
__global__ __launch_bounds__(256, 2)
void prep_kernel(const float* __restrict__ emb,
                 const float* __restrict__ W1,
                 const float* __restrict__ b1,
                 const int* __restrict__ tokens,
                 const float* __restrict__ Wd,
                 const float* __restrict__ U1,
                 const float* __restrict__ W2,
                 const float* __restrict__ U2)
{
    const int bid = blockIdx.x;
    const int tid = threadIdx.x;

    if (bid >= 16512) {
        // ---- transU role: U[512][2048] fp32 -> g_ut[mat][2048][512] fp16 ----
        __shared__ __half sh2[32][33];
        int tb = bid - 16512;
        int mat = tb >> 10;
        int t2 = tb & 1023;
        int k0 = (t2 & 15) * 32;
        int g0 = (t2 >> 4) * 32;
        const float* src = (mat == 0) ? U1 : (mat == 1) ? W2 : U2;
        int tx = tid & 31, ty = tid >> 5;
#pragma unroll
        for (int j = 0; j < 4; j++) {
            int kr = ty + j * 8;
            sh2[kr][tx] = __float2half(src[(size_t)(k0 + kr) * G4H + g0 + tx]);
        }
        __syncthreads();
#pragma unroll
        for (int j = 0; j < 4; j++) {
            int gr = ty + j * 8;
            g_ut[(size_t)mat * G4H * HH + (size_t)(g0 + gr) * HH + k0 + tx] = sh2[tx][gr];
        }
        return;
    }
    if (bid >= 512) {
        // ---- transB role: Wd[512][32000] -> g_b_h[32000][512] fp16 ----
        __shared__ __half sh[32][33];
        int tb = bid - 512;
        int v0 = (tb % 1000) * 32;
        int h0 = (tb / 1000) * 32;
        int tx = tid & 31, ty = tid >> 5;
#pragma unroll
        for (int j = 0; j < 4; j++) {
            int hr = ty + j * 8;
            sh[hr][tx] = __float2half(Wd[(size_t)(h0 + hr) * VV + v0 + tx]);
        }
        __syncthreads();
#pragma unroll
        for (int j = 0; j < 4; j++) {
            int vr = ty + j * 8;
            g_b_h[(size_t)(v0 + vr) * HH + h0 + tx] = sh[tx][vr];
        }
        return;
    }

    // ---- sgemm0 role ----
    const int K = EE, N = G4H;
    __shared__ float As[16][128];
    __shared__ float Bs[16][128];

    const int m0 = (bid >> 4) * 128;
    const int n0 = (bid & 15) * 128;
    const int rg = (tid >> 4) * 4;
    const int cg = (tid & 15) * 4;

    float acc[8][8];
#pragma unroll
    for (int i = 0; i < 8; i++)
#pragma unroll
        for (int j = 0; j < 8; j++) acc[i][j] = 0.f;

    for (int kt = 0; kt < K; kt += 16) {
        __syncthreads();
#pragma unroll
        for (int it = 0; it < 2; it++) {
            int item = tid + it * 256;
            int m = item >> 2;
            int kq = item & 3;
            int gr = m0 + m;
            int tok = tokens[((gr & 15) << 8) + (gr >> 4)];
            float4 v = *(const float4*)(emb + (size_t)tok * K + kt + kq * 4);
            As[kq * 4 + 0][m] = v.x;
            As[kq * 4 + 1][m] = v.y;
            As[kq * 4 + 2][m] = v.z;
            As[kq * 4 + 3][m] = v.w;
        }
#pragma unroll
        for (int it = 0; it < 2; it++) {
            int item = tid + it * 256;
            int k = item >> 5;
            int n4 = item & 31;
            float4 v = *(const float4*)(W1 + (size_t)(kt + k) * N + n0 + n4 * 4);
            *(float4*)&Bs[k][n4 * 4] = v;
        }
        __syncthreads();
#pragma unroll
        for (int kk = 0; kk < 16; kk++) {
            float4 a0 = *(const float4*)&As[kk][rg];
            float4 a1 = *(const float4*)&As[kk][64 + rg];
            float4 b0 = *(const float4*)&Bs[kk][cg];
            float4 b1 = *(const float4*)&Bs[kk][64 + cg];
            float a[8] = {a0.x, a0.y, a0.z, a0.w, a1.x, a1.y, a1.z, a1.w};
            float b[8] = {b0.x, b0.y, b0.z, b0.w, b1.x, b1.y, b1.z, b1.w};
#pragma unroll
            for (int i = 0; i < 8; i++)
#pragma unroll
                for (int j = 0; j < 8; j++)
                    acc[i][j] += a[i] * b[j];
        }
    }

    float bj[8];
#pragma unroll
    for (int j = 0; j < 4; j++) {
        bj[j]     = b1[n0 + cg + j];
        bj[4 + j] = b1[n0 + 64 + cg + j];
    }
#pragma unroll
    for (int i = 0; i < 8; i++) {
        int r = m0 + ((i < 4) ? (rg + i) : (64 + rg + i - 4));
        float4 o0, o1;
        o0.x = acc[i][0] + bj[0]; o0.y = acc[i][1] + bj[1];
        o0.z = acc[i][2] + bj[2]; o0.w = acc[i][3] + bj[3];
        o1.x = acc[i][4] + bj[4]; o1.y = acc[i][5] + bj[5];
        o1.z = acc[i][6] + bj[6]; o1.w = acc[i][7] + bj[7];
        *(float4*)&g_xw[(size_t)r * N + n0 + cg]      = o0;
        *(float4*)&g_xw[(size_t)r * N + n0 + 64 + cg] = o1;
    }
}

// ------------------------- fused dual-layer LSTM on tensor cores ----------------
// 128 CTAs x 256 threads (8 warps), persistent. CTA owns 4 hidden units for BOTH
// layers (16 gate cols each). Step s: h1[s] (s<256) and h2[s-1] (s>=1).
// 12 jobs = {U1,W2,U2} x 4 k-slices(128); warp w does jobs {w, w+8<12}.
// All operands fp16, fp32 accum via mma.m16n8k16; B slices SMEM-resident.
// Row stride 1040 B (520 halfs) -> conflict-free ldmatrix.
// SMEM bytes: Bsl 49920 | h1st 16640 | h2st 16640 | zp 12288 | zsh 2048 | cs 512
#define LSTM_SMEM 98048
__global__ __launch_bounds__(256, 1)
void lstm_tc_kernel(const float* __restrict__ b2)
{
    extern __shared__ char lsm[];
    char* Bsl = lsm;                       // 3*16*1040
    char* h1st = lsm + 49920;              // 16*1040
    char* h2st = lsm + 66560;              // 16*1040
    float* zp = (float*)(lsm + 83200);     // [12][16][16]
    float* zsh1 = (float*)(lsm + 95488);   // [256]
    float* zsh2 = (float*)(lsm + 96512);   // [256]
    float* cs = (float*)(lsm + 97536);     // c1[64] c2[64]

    const int tid = threadIdx.x;
    const int wid = tid >> 5;
    const int lane = tid & 31;
    const int ct = blockIdx.x;
    const int hu0 = ct * 4;
    const uint32_t Bsl_a = smem_u32(Bsl);
    const uint32_t h1_a = smem_u32(h1st);
    const uint32_t h2_a = smem_u32(h2st);

    // ---- init: load B slices (g_ut rows are coalesced 1KB) ----
    for (int i = tid; i < 3072; i += 256) {
        int mat = i >> 10;
        int rem = i & 1023;
        int n = rem >> 6;
        int ch = rem & 63;
        int gc = (n >> 2) * HH + hu0 + (n & 3);
        cp_async16(Bsl_a + (uint32_t)(mat * 16640 + n * 1040 + ch * 16),
                   g_ut + (size_t)mat * G4H * HH + (size_t)gc * HH + ch * 8);
    }
    cp_commit();
    // zero h stages (2 x 16640 B contiguous)
    for (int i = tid; i < 2080; i += 256)
        *(uint4*)(h1st + i * 16) = make_uint4(0, 0, 0, 0);
    if (tid < 128) cs[tid] = 0.f;
    cp_wait<0>();
    __syncthreads();

    // reduce-role constants: thread = (b = tid/16, n = tid%16)
    const int rb = tid >> 4;
    const int rn = tid & 15;
    const int rgc = (rn >> 2) * HH + hu0 + (rn & 3);
    const float b2v = __ldg(b2 + rgc);

    const uint32_t lrow = (uint32_t)(lane & 15) * 1040u;
    const uint32_t lsel = (uint32_t)((lane >> 4) << 4);

    for (int s = 0; s <= TT; s++) {
        // ---- stage h1[s-1], h2[s-2] as fp16 (1024 chunks each) ----
        if (s >= 1) {
            const __half* hp = g_h1rh[(s - 1) & 1];
#pragma unroll
            for (int i = 0; i < 4; i++) {
                int u = tid + i * 256;        // 0..1023
                int b = u >> 6, ch = u & 63;
                cp_async16(h1_a + (uint32_t)(b * 1040 + ch * 16), hp + b * HH + ch * 8);
            }
            if (s >= 2) {
                const __half* hq = g_h2rh[s & 1];
#pragma unroll
                for (int i = 0; i < 4; i++) {
                    int u = tid + i * 256;
                    int b = u >> 6, ch = u & 63;
                    cp_async16(h2_a + (uint32_t)(b * 1040 + ch * 16), hq + b * HH + ch * 8);
                }
            }
            cp_commit();
            cp_wait<0>();
        }
        __syncthreads();

        // ---- tensor-core matvecs: up to 2 jobs per warp ----
#pragma unroll
        for (int jj = 0; jj < 2; jj++) {
            int j = wid + jj * 8;
            if (j < 12) {
                int mat = j >> 2, ksl = j & 3;
                uint32_t Ab = ((mat == 2) ? h2_a : h1_a) + (uint32_t)(ksl * 256) + lrow + lsel;
                uint32_t Bb = Bsl_a + (uint32_t)(mat * 16640 + ksl * 256) + lrow + lsel;
                float acc[2][4] = {{0.f, 0.f, 0.f, 0.f}, {0.f, 0.f, 0.f, 0.f}};
#pragma unroll
                for (int c = 0; c < 8; c++) {
                    uint32_t a[4], bf[4];
                    ldm_x4(a, Ab + (uint32_t)(c * 32));
                    ldm_x4(bf, Bb + (uint32_t)(c * 32));
                    mma_f16(acc[0], a, bf[0], bf[2]);
                    mma_f16(acc[1], a, bf[1], bf[3]);
                }
                int r0 = lane >> 2, c0 = (lane & 3) * 2;
                float* zj = zp + j * 256;
#pragma unroll
                for (int nt = 0; nt < 2; nt++) {
                    zj[r0 * 16 + nt * 8 + c0]           = acc[nt][0];
                    zj[r0 * 16 + nt * 8 + c0 + 1]       = acc[nt][1];
                    zj[(r0 + 8) * 16 + nt * 8 + c0]     = acc[nt][2];
                    zj[(r0 + 8) * 16 + nt * 8 + c0 + 1] = acc[nt][3];
                }
            }
        }
        __syncthreads();

        // ---- reduce over 4 k-slices ----
        {
            float z1 = (s < TT) ? __ldg(&g_xw[((size_t)s * BB + rb) * G4H + rgc]) : 0.f;
            float z2 = b2v;
            int o = rb * 16 + rn;
#pragma unroll
            for (int ksl = 0; ksl < 4; ksl++) {
                z1 += zp[ksl * 256 + o];
                z2 += zp[(4 + ksl) * 256 + o] + zp[(8 + ksl) * 256 + o];
            }
            zsh1[o] = z1;
            zsh2[o] = z2;
        }
        __syncthreads();

        // ---- gates: tid<64 layer1, 64..127 layer2 ----
        if (tid < 64) {
            if (s < TT) {
                int b = tid >> 2, u = tid & 3;
                float zi = zsh1[b * 16 + u];
                float zf = zsh1[b * 16 + 4 + u];
                float zg = zsh1[b * 16 + 8 + u];
                float zo = zsh1[b * 16 + 12 + u];
                float ig = 1.f / (1.f + expf(-zi));
                float fg = 1.f / (1.f + expf(-zf));
                float gg = tanhf(zg);
                float og = 1.f / (1.f + expf(-zo));
                float c = fg * cs[tid] + ig * gg;
                cs[tid] = c;
                g_h1rh[s & 1][b * HH + hu0 + u] = __float2half(og * tanhf(c));
                __threadfence();
            }
        } else if (tid < 128) {
            if (s >= 1) {
                int w = tid - 64;
                int b = w >> 2, u = w & 3;
                int t = s - 1;
                float zi = zsh2[b * 16 + u];
                float zf = zsh2[b * 16 + 4 + u];
                float zg = zsh2[b * 16 + 8 + u];
                float zo = zsh2[b * 16 + 12 + u];
                float ig = 1.f / (1.f + expf(-zi));
                float fg = 1.f / (1.f + expf(-zf));
                float gg = tanhf(zg);
                float og = 1.f / (1.f + expf(-zo));
                float c = fg * cs[tid] + ig * gg;
                cs[tid] = c;
                float h = og * tanhf(c);
                __half hh = __float2half(h);
                g_h2rh[t & 1][b * HH + hu0 + u] = hh;
                g_a_h[((size_t)t * BB + b) * HH + hu0 + u] = hh;
                __threadfence();
            }
        }
        grid_barrier(NCTA);
    }
}

// ------------------------- HMMA dense GEMM (fp16, 3-stage pipeline) -------------
#define DARR 10240u          // bytes per sub-array (128*80)
#define DSTG 20480u          // bytes per stage (A|B)

__device__ __forceinline__ void dense_load_chunk(uint32_t sb, int m0, int n0, int c, int tid)
{
    const uint32_t stg = sb + (uint32_t)(c % 3) * DSTG;
    const int kc0 = c * 32;
#pragma unroll
    for (int it = 0; it < 4; it++) {
        int u = tid + it * 256;          // 0..1023 16B units
        int arr = u >> 9;                // 0 A, 1 B
        int u2 = u & 511;
        int r = u2 >> 2, q = u2 & 3;
        const __half* g = arr ? g_b_h : g_a_h;
        int grow = arr ? n0 : m0;
        cp_async16(stg + (uint32_t)arr * DARR + (uint32_t)(r * 80 + q * 16),
                   g + (size_t)(grow + r) * HH + kc0 + q * 8);
    }
    cp_commit();
}

__global__ __launch_bounds__(256, 2)
void dense_kernel(const float* __restrict__ bd, float* __restrict__ out)
{
    extern __shared__ char smem[];
    const uint32_t sb = smem_u32(smem);
    const int tid = threadIdx.x;
    const int wid = tid >> 5;
    const int lane = tid & 31;
    const int n0 = blockIdx.x * 128;
    const int m0 = blockIdx.y * 128;
    const int wm = wid & 1;
    const int wn = wid >> 1;
    const int lrow = lane & 15;
    const int lsel = (lane >> 4) << 4;

    float acc[4][4][4];
#pragma unroll
    for (int mt = 0; mt < 4; mt++)
#pragma unroll
        for (int nt = 0; nt < 4; nt++)
#pragma unroll
            for (int e = 0; e < 4; e++) acc[mt][nt][e] = 0.f;

    dense_load_chunk(sb, m0, n0, 0, tid);
    dense_load_chunk(sb, m0, n0, 1, tid);

    for (int c = 0; c < 16; c++) {
        if (c < 15) cp_wait<1>(); else cp_wait<0>();
        __syncthreads();
        if (c + 2 < 16) dense_load_chunk(sb, m0, n0, c + 2, tid);

        const uint32_t stg = sb + (uint32_t)(c % 3) * DSTG;
        const uint32_t a_b = stg + (uint32_t)((wm * 64 + lrow) * 80) + lsel;
        const uint32_t b_b = stg + DARR + (uint32_t)((wn * 32 + lrow) * 80) + lsel;
#pragma unroll
        for (int s = 0; s < 2; s++) {
            uint32_t bf[2][4];
#pragma unroll
            for (int i = 0; i < 2; i++)
                ldm_x4(bf[i], b_b + (uint32_t)(i * 16 * 80 + s * 32));
#pragma unroll
            for (int mt = 0; mt < 4; mt++) {
                uint32_t a[4];
                ldm_x4(a, a_b + (uint32_t)(mt * 16 * 80 + s * 32));
#pragma unroll
                for (int nt = 0; nt < 4; nt++) {
                    uint32_t b0 = bf[nt >> 1][nt & 1];
                    uint32_t b1 = bf[nt >> 1][(nt & 1) + 2];
                    mma_f16(acc[mt][nt], a, b0, b1);
                }
            }
        }
    }

    // epilogue: direct stores with [t*16+b] -> [b*256+t] row remap
    const int g = lane >> 2;
    const int tig = lane & 3;
#pragma unroll
    for (int nt = 0; nt < 4; nt++) {
        int col = n0 + wn * 32 + nt * 8 + tig * 2;
        float b0 = __ldg(bd + col);
        float b1 = __ldg(bd + col + 1);
#pragma unroll
        for (int mt = 0; mt < 4; mt++) {
            int r0 = m0 + wm * 64 + mt * 16 + g;
            int r1 = r0 + 8;
            size_t o0 = (size_t)((r0 & 15) * 256 + (r0 >> 4));
            size_t o1 = (size_t)((r1 & 15) * 256 + (r1 >> 4));
            float2 v0 = make_float2(acc[mt][nt][0] + b0, acc[mt][nt][1] + b1);
            float2 v1 = make_float2(acc[mt][nt][2] + b0, acc[mt][nt][3] + b1);
            *(float2*)(out + o0 * VV + col) = v0;
            *(float2*)(out + o1 * VV + col) = v1;
        }
    }
}

// ------------------------- launch -----------------------------------------------
extern "C" void kernel_launch(void* const* d_in, const int* in_sizes, int n_in,
                              void* d_out, int out_size)
{
    const int*   tokens = (const int*)  d_in[0];
    const float* emb    = (const float*)d_in[1];
    const float* W1     = (const float*)d_in[2];
    const float* U1     = (const float*)d_in[3];
    const float* b1     = (const float*)d_in[4];
    const float* W2     = (const float*)d_in[5];
    const float* U2     = (const float*)d_in[6];
    const float* b2     = (const float*)d_in[7];
    const float* Wd     = (const float*)d_in[8];
    const float* bd     = (const float*)d_in[9];
    float* out = (float*)d_out;

    cudaFuncSetAttribute(dense_kernel, cudaFuncAttributeMaxDynamicSharedMemorySize,
                         (int)(3 * DSTG));
    cudaFuncSetAttribute(lstm_tc_kernel, cudaFuncAttributeMaxDynamicSharedMemorySize,
                         LSTM_SMEM);

    // 1) fused prep: xw1 GEMM + Wd transpose + U1/W2/U2 transposed fp16
    prep_kernel<<<512 + 16000 + 3072, 256>>>(emb, W1, b1, tokens, Wd, U1, W2, U2);
    // 2) fused dual-layer LSTM on tensor cores; layer 2 writes fp16 g_a_h
    lstm_tc_kernel<<<NCTA, 256, LSTM_SMEM>>>(b2);
    // 3) logits = h2 @ Wd + bd on HMMA tensor cores (fp16 single pass)
    dense_kernel<<<dim3(VV / 128, MROWS / 128), 256, 3 * DSTG>>>(bd, out);
}